// round 8
// baseline (speedup 1.0000x reference)
#include <cuda_runtime.h>

// LJ_8718783611256: log_prob = -(LJ pair potential + harmonic confinement)
// x: (4, 2048, 3) float32, out: (4,) float32
//
// R7: R6 ran as TWO waves (regs=40 -> 6 blocks/SM -> capacity 888 < grid 1092);
// the 204-block second wave was a 19%-occupancy tail. Cap regs at 32 via
// __launch_bounds__(256, 8) -> capacity 1184 -> one wave, ~59 warps/SM.

#define NB      4
#define NPTS    2048
#define IT      128          // i-rows per tile
#define JT      64           // j-cols per block (half tile)
#define TPB     256
#define NI      4            // i-rows per thread
#define JCHUNK  8            // j-cols per thread
#define NCHUNK  16           // 2048 / 128
#define NTRI    (NCHUNK * (NCHUNK + 1) / 2)  // 136
#define NBLK    (2 * NTRI + 1)               // blocks per batch = 273

__device__ float g_acc[NB];          // zero-initialized at module load
__device__ unsigned int g_cnt[NB];   // zero-initialized at module load

#define RCP(d, s) \
    asm("rcp.approx.f32 %0, %1;" : "=f"(d) : "f"(s))

template <bool DIAG>
__device__ __forceinline__ float lj_chunk(const float4* __restrict__ sj4,
                                          const float* xi, const float* yi,
                                          const float* zi) {
    float acc[NI] = {0.f, 0.f, 0.f, 0.f};
    #pragma unroll
    for (int k = 0; k < JCHUNK; k++) {
        const float4 p = sj4[k];
        #pragma unroll
        for (int r = 0; r < NI; r++) {
            float dx = xi[r] - p.x;
            float dy = yi[r] - p.y;
            float dz = zi[r] - p.z;
            float sq = dx * dx;
            sq = fmaf(dy, dy, sq);
            sq = fmaf(dz, dz, sq);
            if (DIAG) {
                // i == j gives sq == 0 exactly; push to huge -> rcp -> ~0
                sq = (sq == 0.f) ? 3e38f : sq;
            }
            float inv;
            RCP(inv, sq);
            float i3 = inv * inv * inv;          // d^-6
            acc[r] += fmaf(i3, i3, -i3);         // d^-12 - d^-6
        }
    }
    return (acc[0] + acc[1]) + (acc[2] + acc[3]);
}

__global__ __launch_bounds__(TPB, 8) void lj_tri_kernel(const float* __restrict__ x,
                                                        float* __restrict__ out) {
    const int b = blockIdx.z;
    const float* xb = x + b * NPTS * 3;
    const int t = threadIdx.x;
    const int w = t >> 5, lane = t & 31;

    float contrib = 0.f;   // this block's contribution (thread 0 only)

    if (blockIdx.x == NBLK - 1) {
        // ---------------- harmonic block ----------------
        float sx = 0.f, sy = 0.f, sz = 0.f, s2 = 0.f;
        for (int i = t; i < NPTS; i += TPB) {
            float px = xb[3 * i + 0];
            float py = xb[3 * i + 1];
            float pz = xb[3 * i + 2];
            sx += px; sy += py; sz += pz;
            s2 = fmaf(px, px, s2);
            s2 = fmaf(py, py, s2);
            s2 = fmaf(pz, pz, s2);
        }
        #pragma unroll
        for (int o = 16; o; o >>= 1) {
            sx += __shfl_xor_sync(0xffffffffu, sx, o);
            sy += __shfl_xor_sync(0xffffffffu, sy, o);
            sz += __shfl_xor_sync(0xffffffffu, sz, o);
            s2 += __shfl_xor_sync(0xffffffffu, s2, o);
        }
        __shared__ float red[4][TPB / 32];
        if (lane == 0) { red[0][w] = sx; red[1][w] = sy; red[2][w] = sz; red[3][w] = s2; }
        __syncthreads();
        if (t == 0) {
            float tx = 0.f, ty = 0.f, tz = 0.f, t2 = 0.f;
            #pragma unroll
            for (int k = 0; k < TPB / 32; k++) {
                tx += red[0][k]; ty += red[1][k]; tz += red[2][k]; t2 += red[3][k];
            }
            float com2 = (tx * tx + ty * ty + tz * tz) * (1.0f / NPTS);
            contrib = -0.25f * (t2 - com2);  // -(0.5 * k(=0.5) * sum((x-com)^2))
        }
    } else {
        // ---------------- LJ half-tile block ----------------
        const int tid  = blockIdx.x >> 1;   // triangle tile id
        const int half = blockIdx.x & 1;    // which j-half of the 128-tile

        int by = (int)((sqrtf(8.0f * tid + 1.0f) - 1.0f) * 0.5f);
        while ((by + 1) * (by + 2) / 2 <= tid) by++;
        while (by * (by + 1) / 2 > tid) by--;
        const int bx = tid - by * (by + 1) / 2;
        const bool diag = (bx == by);

        __shared__ float4 sj[JT];
        const int j0 = bx * 128 + half * JT;
        if (t < JT) {
            const float* p = xb + (j0 + t) * 3;
            sj[t] = make_float4(p[0], p[1], p[2], 0.f);
        }
        __syncthreads();

        // thread -> 4 i-rows + 8-j chunk
        const int ig = t & 31;           // i-group: rows ig*4 .. ig*4+3
        const int jh = t >> 5;           // j-chunk: cols jh*8 .. jh*8+7
        const int ibase = by * IT + ig * NI;

        float xi[NI], yi[NI], zi[NI];
        #pragma unroll
        for (int r = 0; r < NI; r++) {
            const float* p = xb + (ibase + r) * 3;
            xi[r] = p[0];
            yi[r] = p[1];
            zi[r] = p[2];
        }

        const float4* sj4 = sj + jh * JCHUNK;
        float pot = diag ? lj_chunk<true>(sj4, xi, yi, zi)
                         : lj_chunk<false>(sj4, xi, yi, zi);
        pot *= 4.0f;

        #pragma unroll
        for (int o = 16; o; o >>= 1)
            pot += __shfl_xor_sync(0xffffffffu, pot, o);

        __shared__ float wsum[TPB / 32];
        if (lane == 0) wsum[w] = pot;
        __syncthreads();

        if (t == 0) {
            float v = 0.f;
            #pragma unroll
            for (int k = 0; k < TPB / 32; k++) v += wsum[k];
            // off-diag tiles: each unordered pair once (weight 1);
            // diag tiles: full ordered tile (weight 0.5). Negate for log_prob.
            contrib = diag ? (-0.5f * v) : (-v);
        }
    }

    // ---------------- accumulate + last-block finalize ----------------
    if (t == 0) {
        atomicAdd(&g_acc[b], contrib);
        __threadfence();
        unsigned int done = atomicAdd(&g_cnt[b], 1u);
        if (done == NBLK - 1) {
            out[b] = g_acc[b];
            g_acc[b] = 0.f;      // reset for next graph replay
            g_cnt[b] = 0u;
        }
    }
}

extern "C" void kernel_launch(void* const* d_in, const int* in_sizes, int n_in,
                              void* d_out, int out_size) {
    const float* x = (const float*)d_in[0];
    float* out = (float*)d_out;

    dim3 grid(NBLK, 1, NB);  // 272 half-tiles + 1 harmonic, x4 batches = 1092
    lj_tri_kernel<<<grid, TPB>>>(x, out);
}

// round 9
// speedup vs baseline: 1.7804x; 1.7804x over previous
#include <cuda_runtime.h>

// LJ_8718783611256: log_prob = -(LJ pair potential + harmonic confinement)
// x: (4, 2048, 3) float32, out: (4,) float32
//
// R8: kernel was MUFU.RCP-throughput-bound (~1.07us per M pairs across all
// configs). Batched reciprocal over the 4 i-rows sharing each j-point:
// 1 RCP + 9 FMUL replaces 4 RCPs -> fma pipe becomes the binder (~6.5us).
// Full 128x128 triangle tiles (548 blocks, one wave), single launch,
// device-global accumulators + last-block finalize (no memset node).

#define NB      4
#define NPTS    2048
#define IT      128          // i-rows per tile
#define JT      128          // j-cols per tile
#define TPB     256
#define NI      4            // i-rows per thread (the reciprocal batch)
#define JCHUNK  16           // j-cols per thread
#define NCHUNK  (NPTS / JT)  // 16
#define NTRI    (NCHUNK * (NCHUNK + 1) / 2)  // 136
#define NBLK    (NTRI + 1)                   // blocks per batch = 137

__device__ float g_acc[NB];          // zero-initialized at module load
__device__ unsigned int g_cnt[NB];   // zero-initialized at module load

#define RCP(d, s) \
    asm("rcp.approx.f32 %0, %1;" : "=f"(d) : "f"(s))

template <bool DIAG>
__device__ __forceinline__ float lj_chunk(const float4* __restrict__ sj4,
                                          const float* xi, const float* yi,
                                          const float* zi) {
    float acc[NI] = {0.f, 0.f, 0.f, 0.f};
    #pragma unroll
    for (int k = 0; k < JCHUNK; k++) {
        const float4 p = sj4[k];
        float s[NI];
        #pragma unroll
        for (int r = 0; r < NI; r++) {
            float dx = xi[r] - p.x;
            float dy = yi[r] - p.y;
            float dz = zi[r] - p.z;
            float sq = dx * dx;
            sq = fmaf(dy, dy, sq);
            sq = fmaf(dz, dz, sq);
            if (DIAG) {
                // i == j gives sq == 0 exactly; sq=1 -> i3=1 -> i3^2-i3 = 0.
                // (Must NOT use a huge value: it would poison the batched product.)
                sq = (sq == 0.f) ? 1.0f : sq;
            }
            s[r] = sq;
        }
        // Batched reciprocal: 1 MUFU for all 4 pairs.
        float p1 = s[0] * s[1];
        float p2 = p1 * s[2];
        float p3 = p2 * s[3];
        float rr;
        RCP(rr, p3);                 // 1/(s0*s1*s2*s3)
        float inv[NI];
        inv[3] = rr * p2;            // 1/s3
        float t = rr * s[3];         // 1/(s0*s1*s2)
        inv[2] = t * p1;             // 1/s2
        float u = t * s[2];          // 1/(s0*s1)
        inv[1] = u * s[0];           // 1/s1
        inv[0] = u * s[1];           // 1/s0
        #pragma unroll
        for (int r = 0; r < NI; r++) {
            float i3 = inv[r] * inv[r] * inv[r];   // d^-6
            acc[r] += fmaf(i3, i3, -i3);           // d^-12 - d^-6
        }
    }
    return (acc[0] + acc[1]) + (acc[2] + acc[3]);
}

__global__ __launch_bounds__(TPB) void lj_tri_kernel(const float* __restrict__ x,
                                                     float* __restrict__ out) {
    const int b = blockIdx.z;
    const float* xb = x + b * NPTS * 3;
    const int t = threadIdx.x;
    const int w = t >> 5, lane = t & 31;

    float contrib = 0.f;   // this block's contribution (thread 0 only)

    if (blockIdx.x == NBLK - 1) {
        // ---------------- harmonic block ----------------
        float sx = 0.f, sy = 0.f, sz = 0.f, s2 = 0.f;
        for (int i = t; i < NPTS; i += TPB) {
            float px = xb[3 * i + 0];
            float py = xb[3 * i + 1];
            float pz = xb[3 * i + 2];
            sx += px; sy += py; sz += pz;
            s2 = fmaf(px, px, s2);
            s2 = fmaf(py, py, s2);
            s2 = fmaf(pz, pz, s2);
        }
        #pragma unroll
        for (int o = 16; o; o >>= 1) {
            sx += __shfl_xor_sync(0xffffffffu, sx, o);
            sy += __shfl_xor_sync(0xffffffffu, sy, o);
            sz += __shfl_xor_sync(0xffffffffu, sz, o);
            s2 += __shfl_xor_sync(0xffffffffu, s2, o);
        }
        __shared__ float red[4][TPB / 32];
        if (lane == 0) { red[0][w] = sx; red[1][w] = sy; red[2][w] = sz; red[3][w] = s2; }
        __syncthreads();
        if (t == 0) {
            float tx = 0.f, ty = 0.f, tz = 0.f, t2 = 0.f;
            #pragma unroll
            for (int k = 0; k < TPB / 32; k++) {
                tx += red[0][k]; ty += red[1][k]; tz += red[2][k]; t2 += red[3][k];
            }
            float com2 = (tx * tx + ty * ty + tz * tz) * (1.0f / NPTS);
            contrib = -0.25f * (t2 - com2);  // -(0.5 * k(=0.5) * sum((x-com)^2))
        }
    } else {
        // ---------------- LJ full-tile block ----------------
        const int tid = blockIdx.x;
        int by = (int)((sqrtf(8.0f * tid + 1.0f) - 1.0f) * 0.5f);
        while ((by + 1) * (by + 2) / 2 <= tid) by++;
        while (by * (by + 1) / 2 > tid) by--;
        const int bx = tid - by * (by + 1) / 2;
        const bool diag = (bx == by);

        __shared__ float4 sj[JT];
        const int j0 = bx * JT;
        if (t < JT) {
            const float* p = xb + (j0 + t) * 3;
            sj[t] = make_float4(p[0], p[1], p[2], 0.f);
        }
        __syncthreads();

        // thread -> 4 i-rows + 16-j chunk
        const int ig = t & 31;           // i-group: rows ig*4 .. ig*4+3
        const int jh = t >> 5;           // j-chunk: cols jh*16 .. jh*16+15
        const int ibase = by * IT + ig * NI;

        float xi[NI], yi[NI], zi[NI];
        #pragma unroll
        for (int r = 0; r < NI; r++) {
            const float* p = xb + (ibase + r) * 3;
            xi[r] = p[0];
            yi[r] = p[1];
            zi[r] = p[2];
        }

        const float4* sj4 = sj + jh * JCHUNK;
        float pot = diag ? lj_chunk<true>(sj4, xi, yi, zi)
                         : lj_chunk<false>(sj4, xi, yi, zi);
        pot *= 4.0f;

        #pragma unroll
        for (int o = 16; o; o >>= 1)
            pot += __shfl_xor_sync(0xffffffffu, pot, o);

        __shared__ float wsum[TPB / 32];
        if (lane == 0) wsum[w] = pot;
        __syncthreads();

        if (t == 0) {
            float v = 0.f;
            #pragma unroll
            for (int k = 0; k < TPB / 32; k++) v += wsum[k];
            // off-diag tiles: each unordered pair once (weight 1);
            // diag tiles: full ordered tile (weight 0.5). Negate for log_prob.
            contrib = diag ? (-0.5f * v) : (-v);
        }
    }

    // ---------------- accumulate + last-block finalize ----------------
    if (t == 0) {
        atomicAdd(&g_acc[b], contrib);
        __threadfence();
        unsigned int done = atomicAdd(&g_cnt[b], 1u);
        if (done == NBLK - 1) {
            out[b] = g_acc[b];
            g_acc[b] = 0.f;      // reset for next graph replay
            g_cnt[b] = 0u;
        }
    }
}

extern "C" void kernel_launch(void* const* d_in, const int* in_sizes, int n_in,
                              void* d_out, int out_size) {
    const float* x = (const float*)d_in[0];
    float* out = (float*)d_out;

    dim3 grid(NBLK, 1, NB);  // 136 full tiles + 1 harmonic, x4 batches = 548
    lj_tri_kernel<<<grid, TPB>>>(x, out);
}